// round 13
// baseline (speedup 1.0000x reference)
#include <cuda_runtime.h>
#include <cstdint>

#define NROWS 1000000
#define H     128
#define K     64
#define TEMP  30.0f
#define TILE_M 128
#define TTOT  ((NROWS + TILE_M - 1) / TILE_M)   // 7813
#define BSTR  144    // k3 B smem row stride (LDS.128 conflict-free)
#define SSTR  136    // k1 zn-tile stride: phase-B banks 8qc+qr -> bijective
#define K1GRID 296   // 2 CTAs/SM guaranteed (70KB smem) -> even waves

// ---------------- scratch (no device mallocs allowed) ----------------
__device__ float    g_sums[K * H];
__device__ float    g_cnts[K];
__device__ uint32_t g_mu32[K * H];   // tf32-rounded mu bits

// ---------------- PTX helpers (baseline PTX only) ----------------
__device__ __forceinline__ uint32_t to_tf32(float f) {
    uint32_t u;
    asm("cvt.rna.tf32.f32 %0, %1;" : "=r"(u) : "f"(f));
    return u;
}
// m16n8k8 tf32 MMA, fp32 accum
__device__ __forceinline__ void mma_tf32(float* c, const uint32_t* a, const uint32_t* b) {
    asm volatile(
        "mma.sync.aligned.m16n8k8.row.col.f32.tf32.tf32.f32 "
        "{%0,%1,%2,%3}, {%4,%5,%6,%7}, {%8,%9}, {%0,%1,%2,%3};"
        : "+f"(c[0]), "+f"(c[1]), "+f"(c[2]), "+f"(c[3])
        : "r"(a[0]), "r"(a[1]), "r"(a[2]), "r"(a[3]), "r"(b[0]), "r"(b[1]));
}

// ---------------------------------------------------------------------------
__global__ void k_zero() {
    int i = blockIdx.x * blockDim.x + threadIdx.x;
    if (i < K * H) g_sums[i] = 0.0f;
    if (i < K)     g_cnts[i] = 0.0f;
}

// ---------------------------------------------------------------------------
// k1: normalize z -> zn AND per-community sums via one-hot tf32 GEMM
//     (no smem atomics). Per 128-row chunk:
//       stage comm (coalesced) + normalize into As -> barrier ->
//       16 m16n8k8 K-steps/warp with B synthesized from comm compares.
//     Register psum flushed once per block via global atomicAdd.
//     Fragment map (m16n8k8): A a0=(qr,qc) a1=(qr+8,qc) a2=(qr,qc+4)
//     a3=(qr+8,qc+4); B b0=(qc,qr) b1=(qc+4,qr); D c0=(qr,2qc) c1=(qr,2qc+1)
//     c2=(qr+8,2qc) c3=(qr+8,2qc+1). m=h-in-16, k=row-in-8, n=comm-in-8.
// ---------------------------------------------------------------------------
__global__ void __launch_bounds__(256)
k_norm_acc(const float* __restrict__ z, const int* __restrict__ comm,
           float* __restrict__ zn) {
    __shared__ float As[TILE_M * SSTR];   // 69632 B
    __shared__ int   sComm[TILE_M];
    __shared__ float sCnt[K];

    int tid  = threadIdx.x;
    int lane = tid & 31;
    int warp = tid >> 5;          // 0..7
    int qr   = lane >> 2;         // 0..7
    int qc   = lane & 3;          // 0..3

    if (tid < K) sCnt[tid] = 0.0f;

    float c[8][4];                // psum: D[h=16*warp+..][comm=8*nt+..]
    #pragma unroll
    for (int nt = 0; nt < 8; nt++)
        #pragma unroll
        for (int q = 0; q < 4; q++) c[nt][q] = 0.0f;

    const int hbase = warp * 16;

    for (int chunk = blockIdx.x; chunk < TTOT; chunk += K1GRID) {
        long rowbase = (long)chunk * TILE_M;

        __syncthreads();   // prev chunk's MMA reads of As/sComm complete

        // Stage comm for the whole chunk (coalesced; counts too).
        if (tid < TILE_M) {
            long row = rowbase + tid;
            int cm = (row < NROWS) ? __ldg(comm + row) : -1;
            sComm[tid] = cm;
            if (cm >= 0) atomicAdd(&sCnt[cm], 1.0f);
        }

        // Phase A: warp-per-row normalize; warp w handles local rows w+8i.
        #pragma unroll 4
        for (int i = 0; i < 16; i++) {
            int  lr  = warp + i * 8;
            long row = rowbase + lr;
            bool ok  = row < NROWS;

            float4 v = make_float4(0.f, 0.f, 0.f, 0.f);
            if (ok) v = ((const float4*)(z + row * (long)H))[lane];
            float ss = v.x * v.x + v.y * v.y + v.z * v.z + v.w * v.w;
            #pragma unroll
            for (int o = 16; o; o >>= 1) ss += __shfl_xor_sync(0xffffffffu, ss, o);
            float inv = rsqrtf(fmaxf(ss, 1e-30f));
            v.x *= inv; v.y *= inv; v.z *= inv; v.w *= inv;

            if (ok) ((float4*)(zn + row * (long)H))[lane] = v;
            *(float4*)&As[lr * SSTR + lane * 4] = v;
        }
        __syncthreads();   // As + sComm visible

        // Phase B: one-hot GEMM accumulate. 16 K-steps of 8 rows.
        #pragma unroll
        for (int s = 0; s < 16; s++) {
            int rb = s * 8;
            uint32_t ua[4];
            ua[0] = to_tf32(As[(rb + qc)     * SSTR + hbase + qr]);
            ua[1] = to_tf32(As[(rb + qc)     * SSTR + hbase + qr + 8]);
            ua[2] = to_tf32(As[(rb + qc + 4) * SSTR + hbase + qr]);
            ua[3] = to_tf32(As[(rb + qc + 4) * SSTR + hbase + qr + 8]);
            int c0 = sComm[rb + qc];
            int c1 = sComm[rb + qc + 4];
            #pragma unroll
            for (int nt = 0; nt < 8; nt++) {
                int kk = nt * 8 + qr;
                uint32_t b[2];
                b[0] = (c0 == kk) ? 0x3F800000u : 0u;
                b[1] = (c1 == kk) ? 0x3F800000u : 0u;
                mma_tf32(c[nt], ua, b);
            }
        }
    }

    // Flush psum -> g_sums (layout [k*H + h]).
    #pragma unroll
    for (int nt = 0; nt < 8; nt++) {
        int k0 = nt * 8 + 2 * qc;
        atomicAdd(&g_sums[(k0)     * H + hbase + qr],     c[nt][0]);
        atomicAdd(&g_sums[(k0 + 1) * H + hbase + qr],     c[nt][1]);
        atomicAdd(&g_sums[(k0)     * H + hbase + qr + 8], c[nt][2]);
        atomicAdd(&g_sums[(k0 + 1) * H + hbase + qr + 8], c[nt][3]);
    }
    __syncthreads();
    if (tid < K) atomicAdd(&g_cnts[tid], sCnt[tid]);
}

// ---------------------------------------------------------------------------
__global__ void k_mu(float* __restrict__ mu) {
    int i = blockIdx.x * blockDim.x + threadIdx.x;
    if (i < K * H) {
        float c = g_cnts[i / H];
        float v = g_sums[i] / fmaxf(c, 1.0f);
        mu[i] = v;
        g_mu32[i] = to_tf32(v);   // pre-rounded tf32 bits for the MMA B operand
    }
}

// ---------------------------------------------------------------------------
// k3: dist = zn @ mu^T via tf32 mma.sync.m16n8k8, fused softmax -> r.
//   R9 version; occupancy 4 -> 6 CTAs/SM (221KB smem/SM) for more DRAM MLP.
// ---------------------------------------------------------------------------
__global__ void __launch_bounds__(128, 6)
k_dist_mma(const float* __restrict__ zn,
           float* __restrict__ r, float* __restrict__ dist) {
    __shared__ uint32_t Bs[K * BSTR];

    int tid  = threadIdx.x;
    long base = (long)blockIdx.x * TILE_M;

    #pragma unroll
    for (int i = 0; i < 16; i++) {
        int idx = i * 128 + tid;
        int row = idx >> 5, ch = idx & 31;
        *(uint4*)&Bs[row * BSTR + ch * 4] = *(const uint4*)(g_mu32 + row * H + ch * 4);
    }
    __syncthreads();

    int lane = tid & 31, wid = tid >> 5;
    int qr = lane >> 2;
    int qc = lane & 3;

    long rowA[2], rowB[2];
    const float* aLo[2];
    const float* aHi[2];
    #pragma unroll
    for (int mt = 0; mt < 2; mt++) {
        rowA[mt] = base + wid * 32 + mt * 16 + qr;
        rowB[mt] = rowA[mt] + 8;
        long ca = rowA[mt] < NROWS ? rowA[mt] : (NROWS - 1);
        long cb = rowB[mt] < NROWS ? rowB[mt] : (NROWS - 1);
        aLo[mt] = zn + ca * (long)H + 4 * qc;
        aHi[mt] = zn + cb * (long)H + 4 * qc;
    }

    const uint32_t* bBase = Bs + qr * BSTR + 4 * qc;

    float c[2][8][4];
    #pragma unroll
    for (int mt = 0; mt < 2; mt++)
        #pragma unroll
        for (int n = 0; n < 8; n++)
            #pragma unroll
            for (int q = 0; q < 4; q++) c[mt][n][q] = 0.0f;

    #pragma unroll
    for (int u = 0; u < 8; u++) {
        int co = u * 16;
        uint32_t ua0[2][4], ua1[2][4];
        #pragma unroll
        for (int mt = 0; mt < 2; mt++) {
            float4 lo = *(const float4*)(aLo[mt] + co);
            float4 hi = *(const float4*)(aHi[mt] + co);
            ua0[mt][0] = to_tf32(lo.x); ua0[mt][1] = to_tf32(hi.x);
            ua0[mt][2] = to_tf32(lo.y); ua0[mt][3] = to_tf32(hi.y);
            ua1[mt][0] = to_tf32(lo.z); ua1[mt][1] = to_tf32(hi.z);
            ua1[mt][2] = to_tf32(lo.w); ua1[mt][3] = to_tf32(hi.w);
        }
        #pragma unroll
        for (int n = 0; n < 8; n++) {
            uint4 b4 = *(const uint4*)(bBase + n * 8 * BSTR + co);
            uint32_t ub0[2] = { b4.x, b4.y };
            uint32_t ub1[2] = { b4.z, b4.w };
            mma_tf32(c[0][n], ua0[0], ub0);
            mma_tf32(c[1][n], ua0[1], ub0);
            mma_tf32(c[0][n], ua1[0], ub1);
            mma_tf32(c[1][n], ua1[1], ub1);
        }
    }

    #pragma unroll
    for (int mt = 0; mt < 2; mt++) {
        float va[16], vb[16];
        #pragma unroll
        for (int n = 0; n < 8; n++) {
            va[2 * n] = c[mt][n][0]; va[2 * n + 1] = c[mt][n][1];
            vb[2 * n] = c[mt][n][2]; vb[2 * n + 1] = c[mt][n][3];
        }

        float mxa = va[0], mxb = vb[0];
        #pragma unroll
        for (int i = 1; i < 16; i++) {
            mxa = fmaxf(mxa, va[i]);
            mxb = fmaxf(mxb, vb[i]);
        }
        mxa = fmaxf(mxa, __shfl_xor_sync(0xffffffffu, mxa, 1));
        mxa = fmaxf(mxa, __shfl_xor_sync(0xffffffffu, mxa, 2));
        mxb = fmaxf(mxb, __shfl_xor_sync(0xffffffffu, mxb, 1));
        mxb = fmaxf(mxb, __shfl_xor_sync(0xffffffffu, mxb, 2));

        float ea[16], eb[16], sa = 0.0f, sbv = 0.0f;
        #pragma unroll
        for (int i = 0; i < 16; i++) {
            ea[i] = __expf(TEMP * (va[i] - mxa)); sa  += ea[i];
            eb[i] = __expf(TEMP * (vb[i] - mxb)); sbv += eb[i];
        }
        sa  += __shfl_xor_sync(0xffffffffu, sa, 1);
        sa  += __shfl_xor_sync(0xffffffffu, sa, 2);
        sbv += __shfl_xor_sync(0xffffffffu, sbv, 1);
        sbv += __shfl_xor_sync(0xffffffffu, sbv, 2);
        float isa = 1.0f / sa, isb = 1.0f / sbv;

        int colb = qc * 2;
        if (rowA[mt] < NROWS) {
            float* dr = dist + rowA[mt] * (long)K + colb;
            float* rr = r    + rowA[mt] * (long)K + colb;
            #pragma unroll
            for (int n = 0; n < 8; n++) {
                *(float2*)(dr + n * 8) = make_float2(va[2 * n], va[2 * n + 1]);
                *(float2*)(rr + n * 8) = make_float2(ea[2 * n] * isa, ea[2 * n + 1] * isa);
            }
        }
        if (rowB[mt] < NROWS) {
            float* dr = dist + rowB[mt] * (long)K + colb;
            float* rr = r    + rowB[mt] * (long)K + colb;
            #pragma unroll
            for (int n = 0; n < 8; n++) {
                *(float2*)(dr + n * 8) = make_float2(vb[2 * n], vb[2 * n + 1]);
                *(float2*)(rr + n * 8) = make_float2(eb[2 * n] * isb, eb[2 * n + 1] * isb);
            }
        }
    }
}

// ---------------------------------------------------------------------------
// kernel_launch: out layout = zn [N*H] | mu [K*H] | r [N*K] | dist [N*K]
// ---------------------------------------------------------------------------
extern "C" void kernel_launch(void* const* d_in, const int* in_sizes, int n_in,
                              void* d_out, int out_size) {
    const float* z    = (const float*)d_in[0];
    const int*   comm = (const int*)d_in[1];

    float* out  = (float*)d_out;
    float* zn   = out;
    float* mu   = zn + (long)NROWS * H;
    float* rr   = mu + (long)K * H;
    float* dist = rr + (long)NROWS * K;

    k_zero<<<(K * H + 255) / 256, 256>>>();
    k_norm_acc<<<K1GRID, 256>>>(z, comm, zn);
    k_mu<<<(K * H + 255) / 256, 256>>>(mu);
    k_dist_mma<<<TTOT, 128>>>(zn, rr, dist);
}

// round 14
// speedup vs baseline: 1.8938x; 1.8938x over previous
#include <cuda_runtime.h>
#include <cstdint>

#define NROWS 1000000
#define H     128
#define K     64
#define TEMP  30.0f
#define TILE_M 128
#define TTOT  ((NROWS + TILE_M - 1) / TILE_M)   // 7813
#define BSTR  144    // k3 B smem row stride (LDS.128 conflict-free)
#define K1BLK 592
#define RPI   4      // rows per warp-iteration in k1 (latency batching)

// ---------------- scratch (no device mallocs allowed) ----------------
__device__ float    g_sums[K * H];
__device__ float    g_cnts[K];
__device__ uint32_t g_mu32[K * H];   // tf32-rounded mu bits

// ---------------- PTX helpers (baseline PTX only) ----------------
__device__ __forceinline__ uint32_t to_tf32(float f) {
    uint32_t u;
    asm("cvt.rna.tf32.f32 %0, %1;" : "=r"(u) : "f"(f));
    return u;
}
// m16n8k8 tf32 MMA, fp32 accum
__device__ __forceinline__ void mma_tf32(float* c, const uint32_t* a, const uint32_t* b) {
    asm volatile(
        "mma.sync.aligned.m16n8k8.row.col.f32.tf32.tf32.f32 "
        "{%0,%1,%2,%3}, {%4,%5,%6,%7}, {%8,%9}, {%0,%1,%2,%3};"
        : "+f"(c[0]), "+f"(c[1]), "+f"(c[2]), "+f"(c[3])
        : "r"(a[0]), "r"(a[1]), "r"(a[2]), "r"(a[3]), "r"(b[0]), "r"(b[1]));
}

// ---------------------------------------------------------------------------
__global__ void k_zero() {
    int i = blockIdx.x * blockDim.x + threadIdx.x;
    if (i < K * H) g_sums[i] = 0.0f;
    if (i < K)     g_cnts[i] = 0.0f;
}

// ---------------------------------------------------------------------------
// k1: row-wise L2 normalize z -> zn, accumulate per-community sums/counts.
//   Latency-batched: each warp processes RPI=4 rows per iteration — all 16
//   LDG.32 issued before any reduction (MLP 16), then the 4 shuffle-reduce
//   chains run interleaved, then stores+atomics. Atomic layout = R9 proven:
//   lane l adds columns l+32q (bank = l, conflict-free for every op).
// ---------------------------------------------------------------------------
__global__ void __launch_bounds__(256)
k_norm_acc(const float* __restrict__ z, const int* __restrict__ comm,
           float* __restrict__ zn) {
    __shared__ float s_sum[K * H];
    __shared__ float s_cnt[K];

    int tid = threadIdx.x;
    for (int i = tid; i < K * H; i += blockDim.x) s_sum[i] = 0.0f;
    if (tid < K) s_cnt[tid] = 0.0f;
    __syncthreads();

    int lane  = tid & 31;
    int warp  = tid >> 5;
    int gwarp = blockIdx.x * 8 + warp;
    const long stride = (long)K1BLK * 8 * RPI;

    for (long b = (long)gwarp * RPI; b < NROWS; b += stride) {
        float v[RPI][4];
        int   cm[RPI];
        bool  ok[RPI];

        // Issue all loads first (MLP = 16 LDG.32 + RPI comm loads)
        #pragma unroll
        for (int j = 0; j < RPI; j++) {
            long row = b + j;
            ok[j] = row < NROWS;
            const float* zr = z + (ok[j] ? row : (NROWS - 1)) * (long)H;
            v[j][0] = zr[lane];
            v[j][1] = zr[lane + 32];
            v[j][2] = zr[lane + 64];
            v[j][3] = zr[lane + 96];
            cm[j] = __ldg(comm + (ok[j] ? row : (NROWS - 1)));
        }

        // Interleaved reductions
        float ss[RPI];
        #pragma unroll
        for (int j = 0; j < RPI; j++)
            ss[j] = v[j][0] * v[j][0] + v[j][1] * v[j][1] +
                    v[j][2] * v[j][2] + v[j][3] * v[j][3];
        #pragma unroll
        for (int o = 16; o; o >>= 1) {
            #pragma unroll
            for (int j = 0; j < RPI; j++)
                ss[j] += __shfl_xor_sync(0xffffffffu, ss[j], o);
        }

        float inv[RPI];
        #pragma unroll
        for (int j = 0; j < RPI; j++) inv[j] = rsqrtf(ss[j]);

        #pragma unroll
        for (int j = 0; j < RPI; j++) {
            #pragma unroll
            for (int q = 0; q < 4; q++) v[j][q] *= inv[j];
        }

        // Stores + atomics
        #pragma unroll
        for (int j = 0; j < RPI; j++) {
            if (!ok[j]) continue;
            long row = b + j;
            float* znr = zn + row * (long)H;
            znr[lane]      = v[j][0];
            znr[lane + 32] = v[j][1];
            znr[lane + 64] = v[j][2];
            znr[lane + 96] = v[j][3];

            float* sb = s_sum + cm[j] * H;
            atomicAdd(sb + lane,      v[j][0]);
            atomicAdd(sb + lane + 32, v[j][1]);
            atomicAdd(sb + lane + 64, v[j][2]);
            atomicAdd(sb + lane + 96, v[j][3]);
            if (lane == 0) atomicAdd(&s_cnt[cm[j]], 1.0f);
        }
    }
    __syncthreads();

    for (int i = tid; i < K * H; i += blockDim.x)
        atomicAdd(&g_sums[i], s_sum[i]);
    if (tid < K) atomicAdd(&g_cnts[tid], s_cnt[tid]);
}

// ---------------------------------------------------------------------------
__global__ void k_mu(float* __restrict__ mu) {
    int i = blockIdx.x * blockDim.x + threadIdx.x;
    if (i < K * H) {
        float c = g_cnts[i / H];
        float v = g_sums[i] / fmaxf(c, 1.0f);
        mu[i] = v;
        g_mu32[i] = to_tf32(v);   // pre-rounded tf32 bits for the MMA B operand
    }
}

// ---------------------------------------------------------------------------
// k3: dist = zn @ mu^T via tf32 mma.sync.m16n8k8, fused softmax -> r.
//   EXACT R9 version (176 us, DRAM 70%, regs 126). Do NOT constrain regs.
// ---------------------------------------------------------------------------
__global__ void __launch_bounds__(128, 4)
k_dist_mma(const float* __restrict__ zn,
           float* __restrict__ r, float* __restrict__ dist) {
    __shared__ uint32_t Bs[K * BSTR];

    int tid  = threadIdx.x;
    long base = (long)blockIdx.x * TILE_M;

    #pragma unroll
    for (int i = 0; i < 16; i++) {
        int idx = i * 128 + tid;
        int row = idx >> 5, ch = idx & 31;
        *(uint4*)&Bs[row * BSTR + ch * 4] = *(const uint4*)(g_mu32 + row * H + ch * 4);
    }
    __syncthreads();

    int lane = tid & 31, wid = tid >> 5;
    int qr = lane >> 2;
    int qc = lane & 3;

    long rowA[2], rowB[2];
    const float* aLo[2];
    const float* aHi[2];
    #pragma unroll
    for (int mt = 0; mt < 2; mt++) {
        rowA[mt] = base + wid * 32 + mt * 16 + qr;
        rowB[mt] = rowA[mt] + 8;
        long ca = rowA[mt] < NROWS ? rowA[mt] : (NROWS - 1);
        long cb = rowB[mt] < NROWS ? rowB[mt] : (NROWS - 1);
        aLo[mt] = zn + ca * (long)H + 4 * qc;
        aHi[mt] = zn + cb * (long)H + 4 * qc;
    }

    const uint32_t* bBase = Bs + qr * BSTR + 4 * qc;

    float c[2][8][4];
    #pragma unroll
    for (int mt = 0; mt < 2; mt++)
        #pragma unroll
        for (int n = 0; n < 8; n++)
            #pragma unroll
            for (int q = 0; q < 4; q++) c[mt][n][q] = 0.0f;

    #pragma unroll
    for (int u = 0; u < 8; u++) {
        int co = u * 16;
        uint32_t ua0[2][4], ua1[2][4];
        #pragma unroll
        for (int mt = 0; mt < 2; mt++) {
            float4 lo = *(const float4*)(aLo[mt] + co);
            float4 hi = *(const float4*)(aHi[mt] + co);
            ua0[mt][0] = to_tf32(lo.x); ua0[mt][1] = to_tf32(hi.x);
            ua0[mt][2] = to_tf32(lo.y); ua0[mt][3] = to_tf32(hi.y);
            ua1[mt][0] = to_tf32(lo.z); ua1[mt][1] = to_tf32(hi.z);
            ua1[mt][2] = to_tf32(lo.w); ua1[mt][3] = to_tf32(hi.w);
        }
        #pragma unroll
        for (int n = 0; n < 8; n++) {
            uint4 b4 = *(const uint4*)(bBase + n * 8 * BSTR + co);
            uint32_t ub0[2] = { b4.x, b4.y };
            uint32_t ub1[2] = { b4.z, b4.w };
            mma_tf32(c[0][n], ua0[0], ub0);
            mma_tf32(c[1][n], ua0[1], ub0);
            mma_tf32(c[0][n], ua1[0], ub1);
            mma_tf32(c[1][n], ua1[1], ub1);
        }
    }

    #pragma unroll
    for (int mt = 0; mt < 2; mt++) {
        float va[16], vb[16];
        #pragma unroll
        for (int n = 0; n < 8; n++) {
            va[2 * n] = c[mt][n][0]; va[2 * n + 1] = c[mt][n][1];
            vb[2 * n] = c[mt][n][2]; vb[2 * n + 1] = c[mt][n][3];
        }

        float mxa = va[0], mxb = vb[0];
        #pragma unroll
        for (int i = 1; i < 16; i++) {
            mxa = fmaxf(mxa, va[i]);
            mxb = fmaxf(mxb, vb[i]);
        }
        mxa = fmaxf(mxa, __shfl_xor_sync(0xffffffffu, mxa, 1));
        mxa = fmaxf(mxa, __shfl_xor_sync(0xffffffffu, mxa, 2));
        mxb = fmaxf(mxb, __shfl_xor_sync(0xffffffffu, mxb, 1));
        mxb = fmaxf(mxb, __shfl_xor_sync(0xffffffffu, mxb, 2));

        float ea[16], eb[16], sa = 0.0f, sbv = 0.0f;
        #pragma unroll
        for (int i = 0; i < 16; i++) {
            ea[i] = __expf(TEMP * (va[i] - mxa)); sa  += ea[i];
            eb[i] = __expf(TEMP * (vb[i] - mxb)); sbv += eb[i];
        }
        sa  += __shfl_xor_sync(0xffffffffu, sa, 1);
        sa  += __shfl_xor_sync(0xffffffffu, sa, 2);
        sbv += __shfl_xor_sync(0xffffffffu, sbv, 1);
        sbv += __shfl_xor_sync(0xffffffffu, sbv, 2);
        float isa = 1.0f / sa, isb = 1.0f / sbv;

        int colb = qc * 2;
        if (rowA[mt] < NROWS) {
            float* dr = dist + rowA[mt] * (long)K + colb;
            float* rr = r    + rowA[mt] * (long)K + colb;
            #pragma unroll
            for (int n = 0; n < 8; n++) {
                *(float2*)(dr + n * 8) = make_float2(va[2 * n], va[2 * n + 1]);
                *(float2*)(rr + n * 8) = make_float2(ea[2 * n] * isa, ea[2 * n + 1] * isa);
            }
        }
        if (rowB[mt] < NROWS) {
            float* dr = dist + rowB[mt] * (long)K + colb;
            float* rr = r    + rowB[mt] * (long)K + colb;
            #pragma unroll
            for (int n = 0; n < 8; n++) {
                *(float2*)(dr + n * 8) = make_float2(vb[2 * n], vb[2 * n + 1]);
                *(float2*)(rr + n * 8) = make_float2(eb[2 * n] * isb, eb[2 * n + 1] * isb);
            }
        }
    }
}

// ---------------------------------------------------------------------------
// kernel_launch: out layout = zn [N*H] | mu [K*H] | r [N*K] | dist [N*K]
// ---------------------------------------------------------------------------
extern "C" void kernel_launch(void* const* d_in, const int* in_sizes, int n_in,
                              void* d_out, int out_size) {
    const float* z    = (const float*)d_in[0];
    const int*   comm = (const int*)d_in[1];

    float* out  = (float*)d_out;
    float* zn   = out;
    float* mu   = zn + (long)NROWS * H;
    float* rr   = mu + (long)K * H;
    float* dist = rr + (long)NROWS * K;

    k_zero<<<(K * H + 255) / 256, 256>>>();
    k_norm_acc<<<K1BLK, 256>>>(z, comm, zn);
    k_mu<<<(K * H + 255) / 256, 256>>>(mu);
    k_dist_mma<<<TTOT, 128>>>(zn, rr, dist);
}

// round 15
// speedup vs baseline: 1.9178x; 1.0126x over previous
#include <cuda_runtime.h>
#include <cstdint>

#define NROWS 1000000
#define H     128
#define K     64
#define TEMP  30.0f
#define TILE_M 128
#define TTOT  ((NROWS + TILE_M - 1) / TILE_M)   // 7813
#define BSTR  144    // k3 B smem row stride (LDS.128 conflict-free)
#define K1BLK 592
#define RPI   4      // rows per warp-iteration in k1 (latency batching)

// ---------------- scratch (no device mallocs allowed) ----------------
// Zero-initialized at module load; k_mu consumes-and-resets every call,
// so graph replays always see zeros (k_zero kernel eliminated).
__device__ float    g_sums[K * H];
__device__ float    g_cnts[K];
__device__ uint32_t g_mu32[K * H];   // tf32-rounded mu bits

// ---------------- PTX helpers (baseline PTX only) ----------------
__device__ __forceinline__ uint32_t to_tf32(float f) {
    uint32_t u;
    asm("cvt.rna.tf32.f32 %0, %1;" : "=r"(u) : "f"(f));
    return u;
}
// m16n8k8 tf32 MMA, fp32 accum
__device__ __forceinline__ void mma_tf32(float* c, const uint32_t* a, const uint32_t* b) {
    asm volatile(
        "mma.sync.aligned.m16n8k8.row.col.f32.tf32.tf32.f32 "
        "{%0,%1,%2,%3}, {%4,%5,%6,%7}, {%8,%9}, {%0,%1,%2,%3};"
        : "+f"(c[0]), "+f"(c[1]), "+f"(c[2]), "+f"(c[3])
        : "r"(a[0]), "r"(a[1]), "r"(a[2]), "r"(a[3]), "r"(b[0]), "r"(b[1]));
}

// ---------------------------------------------------------------------------
// k1: row-wise L2 normalize z -> zn, accumulate per-community sums/counts.
//   Latency-batched (R14, at DRAM floor): warp processes RPI=4 rows per
//   iteration, all 16 LDG.32 issued before any reduction, interleaved
//   shuffle chains, then stores+atomics (lane->bank conflict-free).
// ---------------------------------------------------------------------------
__global__ void __launch_bounds__(256)
k_norm_acc(const float* __restrict__ z, const int* __restrict__ comm,
           float* __restrict__ zn) {
    __shared__ float s_sum[K * H];
    __shared__ float s_cnt[K];

    int tid = threadIdx.x;
    for (int i = tid; i < K * H; i += blockDim.x) s_sum[i] = 0.0f;
    if (tid < K) s_cnt[tid] = 0.0f;
    __syncthreads();

    int lane  = tid & 31;
    int warp  = tid >> 5;
    int gwarp = blockIdx.x * 8 + warp;
    const long stride = (long)K1BLK * 8 * RPI;

    for (long b = (long)gwarp * RPI; b < NROWS; b += stride) {
        float v[RPI][4];
        int   cm[RPI];
        bool  ok[RPI];

        #pragma unroll
        for (int j = 0; j < RPI; j++) {
            long row = b + j;
            ok[j] = row < NROWS;
            const float* zr = z + (ok[j] ? row : (NROWS - 1)) * (long)H;
            v[j][0] = zr[lane];
            v[j][1] = zr[lane + 32];
            v[j][2] = zr[lane + 64];
            v[j][3] = zr[lane + 96];
            cm[j] = __ldg(comm + (ok[j] ? row : (NROWS - 1)));
        }

        float ss[RPI];
        #pragma unroll
        for (int j = 0; j < RPI; j++)
            ss[j] = v[j][0] * v[j][0] + v[j][1] * v[j][1] +
                    v[j][2] * v[j][2] + v[j][3] * v[j][3];
        #pragma unroll
        for (int o = 16; o; o >>= 1) {
            #pragma unroll
            for (int j = 0; j < RPI; j++)
                ss[j] += __shfl_xor_sync(0xffffffffu, ss[j], o);
        }

        float inv[RPI];
        #pragma unroll
        for (int j = 0; j < RPI; j++) inv[j] = rsqrtf(ss[j]);

        #pragma unroll
        for (int j = 0; j < RPI; j++) {
            #pragma unroll
            for (int q = 0; q < 4; q++) v[j][q] *= inv[j];
        }

        #pragma unroll
        for (int j = 0; j < RPI; j++) {
            if (!ok[j]) continue;
            long row = b + j;
            float* znr = zn + row * (long)H;
            znr[lane]      = v[j][0];
            znr[lane + 32] = v[j][1];
            znr[lane + 64] = v[j][2];
            znr[lane + 96] = v[j][3];

            float* sb = s_sum + cm[j] * H;
            atomicAdd(sb + lane,      v[j][0]);
            atomicAdd(sb + lane + 32, v[j][1]);
            atomicAdd(sb + lane + 64, v[j][2]);
            atomicAdd(sb + lane + 96, v[j][3]);
            if (lane == 0) atomicAdd(&s_cnt[cm[j]], 1.0f);
        }
    }
    __syncthreads();

    for (int i = tid; i < K * H; i += blockDim.x)
        atomicAdd(&g_sums[i], s_sum[i]);
    if (tid < K) atomicAdd(&g_cnts[tid], s_cnt[tid]);
}

// ---------------------------------------------------------------------------
// k2: mu = sums / counts; consume-and-reset the accumulators for the next
//     graph replay. A 256-thread block covers i in [256b, 256b+256) -> exactly
//     2 communities (H=128), so all readers of a g_cnts entry are in-block;
//     read -> barrier -> zero is race-free.
// ---------------------------------------------------------------------------
__global__ void k_mu(float* __restrict__ mu) {
    int i = blockIdx.x * blockDim.x + threadIdx.x;
    float s = g_sums[i];
    float c = g_cnts[i >> 7];
    __syncthreads();
    g_sums[i] = 0.0f;
    if ((i & 127) == 0) g_cnts[i >> 7] = 0.0f;

    float v = s / fmaxf(c, 1.0f);
    mu[i] = v;
    g_mu32[i] = to_tf32(v);   // B operand: keep rna rounding
}

// ---------------------------------------------------------------------------
// k3: dist = zn @ mu^T via tf32 mma.sync.m16n8k8, fused softmax -> r.
//   R9 structure (regs 126 — DO NOT constrain). Change vs R14: A fragments
//   feed raw fp32 bits to the tf32 MMA (HW truncates to 19 MSBs), removing
//   128 cvt instructions per thread; B stays rna-rounded (g_mu32).
// ---------------------------------------------------------------------------
__global__ void __launch_bounds__(128, 4)
k_dist_mma(const float* __restrict__ zn,
           float* __restrict__ r, float* __restrict__ dist) {
    __shared__ uint32_t Bs[K * BSTR];

    int tid  = threadIdx.x;
    long base = (long)blockIdx.x * TILE_M;

    #pragma unroll
    for (int i = 0; i < 16; i++) {
        int idx = i * 128 + tid;
        int row = idx >> 5, ch = idx & 31;
        *(uint4*)&Bs[row * BSTR + ch * 4] = *(const uint4*)(g_mu32 + row * H + ch * 4);
    }
    __syncthreads();

    int lane = tid & 31, wid = tid >> 5;
    int qr = lane >> 2;
    int qc = lane & 3;

    long rowA[2], rowB[2];
    const float* aLo[2];
    const float* aHi[2];
    #pragma unroll
    for (int mt = 0; mt < 2; mt++) {
        rowA[mt] = base + wid * 32 + mt * 16 + qr;
        rowB[mt] = rowA[mt] + 8;
        long ca = rowA[mt] < NROWS ? rowA[mt] : (NROWS - 1);
        long cb = rowB[mt] < NROWS ? rowB[mt] : (NROWS - 1);
        aLo[mt] = zn + ca * (long)H + 4 * qc;
        aHi[mt] = zn + cb * (long)H + 4 * qc;
    }

    const uint32_t* bBase = Bs + qr * BSTR + 4 * qc;

    float c[2][8][4];
    #pragma unroll
    for (int mt = 0; mt < 2; mt++)
        #pragma unroll
        for (int n = 0; n < 8; n++)
            #pragma unroll
            for (int q = 0; q < 4; q++) c[mt][n][q] = 0.0f;

    #pragma unroll
    for (int u = 0; u < 8; u++) {
        int co = u * 16;
        uint32_t ua0[2][4], ua1[2][4];
        #pragma unroll
        for (int mt = 0; mt < 2; mt++) {
            float4 lo = *(const float4*)(aLo[mt] + co);
            float4 hi = *(const float4*)(aHi[mt] + co);
            ua0[mt][0] = __float_as_uint(lo.x); ua0[mt][1] = __float_as_uint(hi.x);
            ua0[mt][2] = __float_as_uint(lo.y); ua0[mt][3] = __float_as_uint(hi.y);
            ua1[mt][0] = __float_as_uint(lo.z); ua1[mt][1] = __float_as_uint(hi.z);
            ua1[mt][2] = __float_as_uint(lo.w); ua1[mt][3] = __float_as_uint(hi.w);
        }
        #pragma unroll
        for (int n = 0; n < 8; n++) {
            uint4 b4 = *(const uint4*)(bBase + n * 8 * BSTR + co);
            uint32_t ub0[2] = { b4.x, b4.y };
            uint32_t ub1[2] = { b4.z, b4.w };
            mma_tf32(c[0][n], ua0[0], ub0);
            mma_tf32(c[1][n], ua0[1], ub0);
            mma_tf32(c[0][n], ua1[0], ub1);
            mma_tf32(c[1][n], ua1[1], ub1);
        }
    }

    #pragma unroll
    for (int mt = 0; mt < 2; mt++) {
        float va[16], vb[16];
        #pragma unroll
        for (int n = 0; n < 8; n++) {
            va[2 * n] = c[mt][n][0]; va[2 * n + 1] = c[mt][n][1];
            vb[2 * n] = c[mt][n][2]; vb[2 * n + 1] = c[mt][n][3];
        }

        float mxa = va[0], mxb = vb[0];
        #pragma unroll
        for (int i = 1; i < 16; i++) {
            mxa = fmaxf(mxa, va[i]);
            mxb = fmaxf(mxb, vb[i]);
        }
        mxa = fmaxf(mxa, __shfl_xor_sync(0xffffffffu, mxa, 1));
        mxa = fmaxf(mxa, __shfl_xor_sync(0xffffffffu, mxa, 2));
        mxb = fmaxf(mxb, __shfl_xor_sync(0xffffffffu, mxb, 1));
        mxb = fmaxf(mxb, __shfl_xor_sync(0xffffffffu, mxb, 2));

        float ea[16], eb[16], sa = 0.0f, sbv = 0.0f;
        #pragma unroll
        for (int i = 0; i < 16; i++) {
            ea[i] = __expf(TEMP * (va[i] - mxa)); sa  += ea[i];
            eb[i] = __expf(TEMP * (vb[i] - mxb)); sbv += eb[i];
        }
        sa  += __shfl_xor_sync(0xffffffffu, sa, 1);
        sa  += __shfl_xor_sync(0xffffffffu, sa, 2);
        sbv += __shfl_xor_sync(0xffffffffu, sbv, 1);
        sbv += __shfl_xor_sync(0xffffffffu, sbv, 2);
        float isa = 1.0f / sa, isb = 1.0f / sbv;

        int colb = qc * 2;
        if (rowA[mt] < NROWS) {
            float* dr = dist + rowA[mt] * (long)K + colb;
            float* rr = r    + rowA[mt] * (long)K + colb;
            #pragma unroll
            for (int n = 0; n < 8; n++) {
                *(float2*)(dr + n * 8) = make_float2(va[2 * n], va[2 * n + 1]);
                *(float2*)(rr + n * 8) = make_float2(ea[2 * n] * isa, ea[2 * n + 1] * isa);
            }
        }
        if (rowB[mt] < NROWS) {
            float* dr = dist + rowB[mt] * (long)K + colb;
            float* rr = r    + rowB[mt] * (long)K + colb;
            #pragma unroll
            for (int n = 0; n < 8; n++) {
                *(float2*)(dr + n * 8) = make_float2(vb[2 * n], vb[2 * n + 1]);
                *(float2*)(rr + n * 8) = make_float2(eb[2 * n] * isb, eb[2 * n + 1] * isb);
            }
        }
    }
}

// ---------------------------------------------------------------------------
// kernel_launch: out layout = zn [N*H] | mu [K*H] | r [N*K] | dist [N*K]
// ---------------------------------------------------------------------------
extern "C" void kernel_launch(void* const* d_in, const int* in_sizes, int n_in,
                              void* d_out, int out_size) {
    const float* z    = (const float*)d_in[0];
    const int*   comm = (const int*)d_in[1];

    float* out  = (float*)d_out;
    float* zn   = out;
    float* mu   = zn + (long)NROWS * H;
    float* rr   = mu + (long)K * H;
    float* dist = rr + (long)NROWS * K;

    k_norm_acc<<<K1BLK, 256>>>(z, comm, zn);
    k_mu<<<K * H / 256, 256>>>(mu);
    k_dist_mma<<<TTOT, 128>>>(zn, rr, dist);
}